// round 12
// baseline (speedup 1.0000x reference)
#include <cuda_runtime.h>
#include <math.h>

// Problem geometry: x, target are [B=8, C=256, H=128, W=128] float32.
#define BB 8
#define CC 256
#define HW (128 * 128)          // 16384 elements per (b,c) plane
#define PLANES (BB * CC)        // 2048
#define RNPC (1.0 / (double)(BB * HW))  // 1/131072, exact power of two

// Per-plane partial raw power sums, transposed for coalesced epilogue reads:
// g_part[k][plane], k: 0..4 = x S1..S5, 5..9 = y S1..S5.
// Every slot rewritten every launch -> deterministic.
__device__ double g_part[10][PLANES];
// Completion counter; last block resets it -> deterministic across graph replays.
__device__ unsigned int g_counter = 0;

// Accumulate v, v^2..v^5 into 5 fp32 running sums (7 fp instrs).
#define ACC5(v, s1, s2, s3, s4, s5)        \
    do {                                   \
        float _v2 = (v) * (v);             \
        float _v3 = _v2 * (v);             \
        s1 += (v);                         \
        s2 += _v2;                         \
        s3 += _v3;                         \
        s4 = fmaf(_v2, _v2, s4);           \
        s5 = fmaf(_v3, _v2, s5);           \
    } while (0)

// Epilogue isolated in a real (noinline) function so its register demands do
// not perturb the streaming loop's allocation/schedule. Runs once, one block.
__device__ __noinline__ void epilogue(float* __restrict__ out, int tid) {
    const int lane = tid & 31;
    const int warp = tid >> 5;
    const int c = tid;   // channel

    // Partials are L2-resident (written this launch). Dual accumulators for MLP.
    double s[10];
#pragma unroll
    for (int k = 0; k < 10; k++) {
        double t0 = 0.0, t1 = 0.0;
#pragma unroll
        for (int b = 0; b < BB; b += 2) {
            t0 += __ldcg(&g_part[k][b * CC + c]);
            t1 += __ldcg(&g_part[k][(b + 1) * CC + c]);
        }
        s[k] = t0 + t1;
    }

    // Raw moments -> central moments (binomial). RNPC = exact 2^-17.
    double q[5];
    {
        const double mux = s[0] * RNPC, M2x = s[1] * RNPC, M3x = s[2] * RNPC,
                     M4x = s[3] * RNPC, M5x = s[4] * RNPC;
        const double muy = s[5] * RNPC, M2y = s[6] * RNPC, M3y = s[7] * RNPC,
                     M4y = s[8] * RNPC, M5y = s[9] * RNPC;
        const double mux2 = mux * mux, mux3 = mux2 * mux;
        const double muy2 = muy * muy, muy3 = muy2 * muy;

        double m2x = M2x - mux2;
        double m3x = M3x - 3.0 * mux * M2x + 2.0 * mux3;
        double m4x = M4x - 4.0 * mux * M3x + 6.0 * mux2 * M2x - 3.0 * mux2 * mux2;
        double m5x = M5x - 5.0 * mux * M4x + 10.0 * mux2 * M3x - 10.0 * mux3 * M2x +
                     4.0 * mux3 * mux2;

        double m2y = M2y - muy2;
        double m3y = M3y - 3.0 * muy * M2y + 2.0 * muy3;
        double m4y = M4y - 4.0 * muy * M3y + 6.0 * muy2 * M2y - 3.0 * muy2 * muy2;
        double m5y = M5y - 5.0 * muy * M4y + 10.0 * muy2 * M3y - 10.0 * muy3 * M2y +
                     4.0 * muy3 * muy2;

        double d0 = mux - muy;
        double d1 = m2x - m2y;
        double d2 = m3x - m3y;
        double d3 = m4x - m4y;
        double d4 = m5x - m5y;
        q[0] = d0 * d0;
        q[1] = d1 * d1;
        q[2] = d2 * d2;
        q[3] = d3 * d3;
        q[4] = d4 * d4;
    }

    // Tree-reduce the 5 sums across 256 threads.
#pragma unroll
    for (int off = 16; off > 0; off >>= 1) {
#pragma unroll
        for (int k = 0; k < 5; k++)
            q[k] += __shfl_xor_sync(0xFFFFFFFFu, q[k], off);
    }

    __shared__ double fred[8][5];
    if (lane == 0) {
#pragma unroll
        for (int k = 0; k < 5; k++) fred[warp][k] = q[k];
    }
    __syncthreads();

    if (tid == 0) {
        double loss = 0.0;
#pragma unroll
        for (int k = 0; k < 5; k++) {
            double t = 0.0;
#pragma unroll
            for (int w = 0; w < 8; w++) t += fred[w][k];
            loss += sqrt(t);
        }
        out[0] = (float)loss;
    }
}

// Streaming config = R4's proven-best moments kernel (unroll 8, no occ cap).
__global__ __launch_bounds__(256) void styleloss_kernel(const float* __restrict__ x,
                                                        const float* __restrict__ y,
                                                        float* __restrict__ out) {
    const int plane = blockIdx.x;   // b * C + c
    const int tid = threadIdx.x;    // 256 threads
    const int lane = tid & 31;
    const int warp = tid >> 5;

    // ---------------- Phase 1: streaming raw power sums ----------------
    {
        const float4* __restrict__ px =
            reinterpret_cast<const float4*>(x + (size_t)plane * HW);
        const float4* __restrict__ py =
            reinterpret_cast<const float4*>(y + (size_t)plane * HW);

        float sx1 = 0.f, sx2 = 0.f, sx3 = 0.f, sx4 = 0.f, sx5 = 0.f;
        float sy1 = 0.f, sy2 = 0.f, sy3 = 0.f, sy4 = 0.f, sy5 = 0.f;

#pragma unroll 8
        for (int j = 0; j < (HW / 4) / 256; j++) {   // 16 iterations
            float4 vx = __ldcs(&px[tid + j * 256]);  // streaming: no reuse
            float4 vy = __ldcs(&py[tid + j * 256]);
            ACC5(vx.x, sx1, sx2, sx3, sx4, sx5);
            ACC5(vx.y, sx1, sx2, sx3, sx4, sx5);
            ACC5(vx.z, sx1, sx2, sx3, sx4, sx5);
            ACC5(vx.w, sx1, sx2, sx3, sx4, sx5);
            ACC5(vy.x, sy1, sy2, sy3, sy4, sy5);
            ACC5(vy.y, sy1, sy2, sy3, sy4, sy5);
            ACC5(vy.z, sy1, sy2, sy3, sy4, sy5);
            ACC5(vy.w, sy1, sy2, sy3, sy4, sy5);
        }

        // Warp reduce the 10 fp32 sums.
#pragma unroll
        for (int off = 16; off > 0; off >>= 1) {
            sx1 += __shfl_xor_sync(0xFFFFFFFFu, sx1, off);
            sx2 += __shfl_xor_sync(0xFFFFFFFFu, sx2, off);
            sx3 += __shfl_xor_sync(0xFFFFFFFFu, sx3, off);
            sx4 += __shfl_xor_sync(0xFFFFFFFFu, sx4, off);
            sx5 += __shfl_xor_sync(0xFFFFFFFFu, sx5, off);
            sy1 += __shfl_xor_sync(0xFFFFFFFFu, sy1, off);
            sy2 += __shfl_xor_sync(0xFFFFFFFFu, sy2, off);
            sy3 += __shfl_xor_sync(0xFFFFFFFFu, sy3, off);
            sy4 += __shfl_xor_sync(0xFFFFFFFFu, sy4, off);
            sy5 += __shfl_xor_sync(0xFFFFFFFFu, sy5, off);
        }

        __shared__ double red[8][10];
        if (lane == 0) {
            red[warp][0] = (double)sx1;
            red[warp][1] = (double)sx2;
            red[warp][2] = (double)sx3;
            red[warp][3] = (double)sx4;
            red[warp][4] = (double)sx5;
            red[warp][5] = (double)sy1;
            red[warp][6] = (double)sy2;
            red[warp][7] = (double)sy3;
            red[warp][8] = (double)sy4;
            red[warp][9] = (double)sy5;
        }
        __syncthreads();
        if (tid < 10) {
            double t = 0.0;
#pragma unroll
            for (int w = 0; w < 8; w++) t += red[w][tid];
            g_part[tid][plane] = t;
        }
    }

    // ---------------- Phase 2: last block runs the epilogue ----------------
    __shared__ bool is_last;
    __syncthreads();                 // g_part writes issued block-wide
    if (tid == 0) {
        __threadfence();             // publish g_part writes device-wide
        unsigned int n = atomicAdd(&g_counter, 1u);
        is_last = (n == PLANES - 1);
        if (is_last) g_counter = 0;  // reset for next graph replay
    }
    __syncthreads();
    if (!is_last) return;

    epilogue(out, tid);
}

extern "C" void kernel_launch(void* const* d_in, const int* in_sizes, int n_in,
                              void* d_out, int out_size) {
    const float* x = (const float*)d_in[0];
    const float* y = (const float*)d_in[1];
    float* out = (float*)d_out;
    (void)in_sizes; (void)n_in; (void)out_size;

    styleloss_kernel<<<PLANES, 256>>>(x, y, out);
}

// round 13
// speedup vs baseline: 1.0950x; 1.0950x over previous
#include <cuda_runtime.h>
#include <math.h>

// Problem geometry: x, target are [B=8, C=256, H=128, W=128] float32.
#define BB 8
#define CC 256
#define HW (128 * 128)          // 16384 elements per (b,c) plane
#define PLANES (BB * CC)        // 2048
#define RNPC (1.0 / (double)(BB * HW))  // 1/131072, exact power of two

// Per-plane partial raw power sums, transposed for coalesced finalize reads:
// g_part[k][plane], k: 0..4 = x S1..S5, 5..9 = y S1..S5.
// Every slot rewritten every launch -> deterministic.
__device__ double g_part[10][PLANES];

// Accumulate v, v^2..v^5 into 5 fp32 running sums (7 fp instrs).
#define ACC5(v, s1, s2, s3, s4, s5)        \
    do {                                   \
        float _v2 = (v) * (v);             \
        float _v3 = _v2 * (v);             \
        s1 += (v);                         \
        s2 += _v2;                         \
        s3 += _v3;                         \
        s4 = fmaf(_v2, _v2, s4);           \
        s5 = fmaf(_v3, _v2, s5);           \
    } while (0)

// Single-stream burst over one 64KB plane: DRAM row-locality friendly.
// Returns 5 raw power sums in s1..s5. Bitwise-identical accumulation order
// to the interleaved version (x and y sums were always independent).
__device__ __forceinline__ void plane_pass(const float4* __restrict__ p, int tid,
                                           float& s1, float& s2, float& s3,
                                           float& s4, float& s5) {
    s1 = 0.f; s2 = 0.f; s3 = 0.f; s4 = 0.f; s5 = 0.f;
#pragma unroll 8
    for (int j = 0; j < (HW / 4) / 256; j++) {   // 16 iterations
        float4 v = __ldcs(&p[tid + j * 256]);    // streaming: no reuse
        ACC5(v.x, s1, s2, s3, s4, s5);
        ACC5(v.y, s1, s2, s3, s4, s5);
        ACC5(v.z, s1, s2, s3, s4, s5);
        ACC5(v.w, s1, s2, s3, s4, s5);
    }
}

__global__ __launch_bounds__(256) void moments_kernel(const float* __restrict__ x,
                                                      const float* __restrict__ y) {
    const int plane = blockIdx.x;   // b * C + c
    const int tid = threadIdx.x;    // 256 threads
    const int lane = tid & 31;
    const int warp = tid >> 5;

    const float4* __restrict__ px =
        reinterpret_cast<const float4*>(x + (size_t)plane * HW);
    const float4* __restrict__ py =
        reinterpret_cast<const float4*>(y + (size_t)plane * HW);

    // Two single-stream bursts instead of interleaved dual-stream.
    float sx1, sx2, sx3, sx4, sx5;
    float sy1, sy2, sy3, sy4, sy5;
    plane_pass(px, tid, sx1, sx2, sx3, sx4, sx5);
    plane_pass(py, tid, sy1, sy2, sy3, sy4, sy5);

    // Warp reduce the 10 fp32 sums.
#pragma unroll
    for (int off = 16; off > 0; off >>= 1) {
        sx1 += __shfl_xor_sync(0xFFFFFFFFu, sx1, off);
        sx2 += __shfl_xor_sync(0xFFFFFFFFu, sx2, off);
        sx3 += __shfl_xor_sync(0xFFFFFFFFu, sx3, off);
        sx4 += __shfl_xor_sync(0xFFFFFFFFu, sx4, off);
        sx5 += __shfl_xor_sync(0xFFFFFFFFu, sx5, off);
        sy1 += __shfl_xor_sync(0xFFFFFFFFu, sy1, off);
        sy2 += __shfl_xor_sync(0xFFFFFFFFu, sy2, off);
        sy3 += __shfl_xor_sync(0xFFFFFFFFu, sy3, off);
        sy4 += __shfl_xor_sync(0xFFFFFFFFu, sy4, off);
        sy5 += __shfl_xor_sync(0xFFFFFFFFu, sy5, off);
    }

    __shared__ double red[8][10];
    if (lane == 0) {
        red[warp][0] = (double)sx1;
        red[warp][1] = (double)sx2;
        red[warp][2] = (double)sx3;
        red[warp][3] = (double)sx4;
        red[warp][4] = (double)sx5;
        red[warp][5] = (double)sy1;
        red[warp][6] = (double)sy2;
        red[warp][7] = (double)sy3;
        red[warp][8] = (double)sy4;
        red[warp][9] = (double)sy5;
    }
    __syncthreads();
    if (tid < 10) {
        double t = 0.0;
#pragma unroll
        for (int w = 0; w < 8; w++) t += red[w][tid];
        g_part[tid][plane] = t;
    }
}

// One block, 256 threads: thread c handles channel c. No atomics, no DDIV.
__global__ __launch_bounds__(256) void finalize_kernel(float* __restrict__ out) {
    const int c = threadIdx.x;

    double s[10];
#pragma unroll
    for (int k = 0; k < 10; k++) {
        double t0 = 0.0, t1 = 0.0;
#pragma unroll
        for (int b = 0; b < BB; b += 2) {
            t0 += g_part[k][b * CC + c];
            t1 += g_part[k][(b + 1) * CC + c];
        }
        s[k] = t0 + t1;
    }

    // Raw moments -> central moments (binomial). RNPC = exact 2^-17.
    double q[5];
    {
        const double mux = s[0] * RNPC, M2x = s[1] * RNPC, M3x = s[2] * RNPC,
                     M4x = s[3] * RNPC, M5x = s[4] * RNPC;
        const double muy = s[5] * RNPC, M2y = s[6] * RNPC, M3y = s[7] * RNPC,
                     M4y = s[8] * RNPC, M5y = s[9] * RNPC;
        const double mux2 = mux * mux, mux3 = mux2 * mux;
        const double muy2 = muy * muy, muy3 = muy2 * muy;

        double m2x = M2x - mux2;
        double m3x = M3x - 3.0 * mux * M2x + 2.0 * mux3;
        double m4x = M4x - 4.0 * mux * M3x + 6.0 * mux2 * M2x - 3.0 * mux2 * mux2;
        double m5x = M5x - 5.0 * mux * M4x + 10.0 * mux2 * M3x - 10.0 * mux3 * M2x +
                     4.0 * mux3 * mux2;

        double m2y = M2y - muy2;
        double m3y = M3y - 3.0 * muy * M2y + 2.0 * muy3;
        double m4y = M4y - 4.0 * muy * M3y + 6.0 * muy2 * M2y - 3.0 * muy2 * muy2;
        double m5y = M5y - 5.0 * muy * M4y + 10.0 * muy2 * M3y - 10.0 * muy3 * M2y +
                     4.0 * muy3 * muy2;

        double d0 = mux - muy;
        double d1 = m2x - m2y;
        double d2 = m3x - m3y;
        double d3 = m4x - m4y;
        double d4 = m5x - m5y;
        q[0] = d0 * d0;
        q[1] = d1 * d1;
        q[2] = d2 * d2;
        q[3] = d3 * d3;
        q[4] = d4 * d4;
    }

#pragma unroll
    for (int off = 16; off > 0; off >>= 1) {
#pragma unroll
        for (int k = 0; k < 5; k++)
            q[k] += __shfl_xor_sync(0xFFFFFFFFu, q[k], off);
    }

    __shared__ double red[8][5];
    const int lane = c & 31;
    const int warp = c >> 5;
    if (lane == 0) {
#pragma unroll
        for (int k = 0; k < 5; k++) red[warp][k] = q[k];
    }
    __syncthreads();

    if (c == 0) {
        double loss = 0.0;
#pragma unroll
        for (int k = 0; k < 5; k++) {
            double t = 0.0;
#pragma unroll
            for (int w = 0; w < 8; w++) t += red[w][k];
            loss += sqrt(t);
        }
        out[0] = (float)loss;
    }
}

extern "C" void kernel_launch(void* const* d_in, const int* in_sizes, int n_in,
                              void* d_out, int out_size) {
    const float* x = (const float*)d_in[0];
    const float* y = (const float*)d_in[1];
    float* out = (float*)d_out;
    (void)in_sizes; (void)n_in; (void)out_size;

    moments_kernel<<<PLANES, 256>>>(x, y);
    finalize_kernel<<<1, 256>>>(out);
}

// round 17
// speedup vs baseline: 1.1032x; 1.0076x over previous
#include <cuda_runtime.h>
#include <math.h>

// Problem geometry: x, target are [B=8, C=256, H=128, W=128] float32.
#define BB 8
#define CC 256
#define HW (128 * 128)          // 16384 elements per (b,c) plane
#define PLANES (BB * CC)        // 2048
#define RNPC (1.0 / (double)(BB * HW))  // 1/131072, exact power of two

// Per-plane partial raw power sums, transposed for coalesced finalize reads:
// g_part[k][plane], k: 0..4 = x S1..S5, 5..9 = y S1..S5.
// Every slot rewritten every launch -> deterministic.
__device__ double g_part[10][PLANES];

// Accumulate v, v^2..v^5 into 5 fp32 running sums (7 fp instrs).
#define ACC5(v, s1, s2, s3, s4, s5)        \
    do {                                   \
        float _v2 = (v) * (v);             \
        float _v3 = _v2 * (v);             \
        s1 += (v);                         \
        s2 += _v2;                         \
        s3 += _v3;                         \
        s4 = fmaf(_v2, _v2, s4);           \
        s5 = fmaf(_v3, _v2, s5);           \
    } while (0)

// One block = one plane of ONE tensor. Blocks 0..PLANES-1 -> x, rest -> y.
// Within a wave all co-resident CTAs stream the SAME buffer contiguously:
// maximal DRAM row locality (the R13 lever, pushed to wave granularity).
__global__ __launch_bounds__(256) void moments_kernel(const float* __restrict__ x,
                                                      const float* __restrict__ y) {
    const int bid = blockIdx.x;          // 0 .. 2*PLANES-1
    const int tid = threadIdx.x;         // 256 threads
    const int lane = tid & 31;
    const int warp = tid >> 5;

    const int is_y = (bid >= PLANES);
    const int plane = is_y ? bid - PLANES : bid;
    const float* __restrict__ base = is_y ? y : x;
    const float4* __restrict__ p =
        reinterpret_cast<const float4*>(base + (size_t)plane * HW);

    float s1 = 0.f, s2 = 0.f, s3 = 0.f, s4 = 0.f, s5 = 0.f;

#pragma unroll 8
    for (int j = 0; j < (HW / 4) / 256; j++) {   // 16 iterations
        float4 v = __ldcs(&p[tid + j * 256]);    // streaming: no reuse
        ACC5(v.x, s1, s2, s3, s4, s5);
        ACC5(v.y, s1, s2, s3, s4, s5);
        ACC5(v.z, s1, s2, s3, s4, s5);
        ACC5(v.w, s1, s2, s3, s4, s5);
    }

    // Warp reduce the 5 fp32 sums.
#pragma unroll
    for (int off = 16; off > 0; off >>= 1) {
        s1 += __shfl_xor_sync(0xFFFFFFFFu, s1, off);
        s2 += __shfl_xor_sync(0xFFFFFFFFu, s2, off);
        s3 += __shfl_xor_sync(0xFFFFFFFFu, s3, off);
        s4 += __shfl_xor_sync(0xFFFFFFFFu, s4, off);
        s5 += __shfl_xor_sync(0xFFFFFFFFu, s5, off);
    }

    __shared__ double red[8][5];
    if (lane == 0) {
        red[warp][0] = (double)s1;
        red[warp][1] = (double)s2;
        red[warp][2] = (double)s3;
        red[warp][3] = (double)s4;
        red[warp][4] = (double)s5;
    }
    __syncthreads();
    if (tid < 5) {
        double t = 0.0;
#pragma unroll
        for (int w = 0; w < 8; w++) t += red[w][tid];
        g_part[tid + (is_y ? 5 : 0)][plane] = t;
    }
}

// One block, 256 threads: thread c handles channel c. No atomics, no DDIV.
__global__ __launch_bounds__(256) void finalize_kernel(float* __restrict__ out) {
    const int c = threadIdx.x;

    double s[10];
#pragma unroll
    for (int k = 0; k < 10; k++) {
        double t0 = 0.0, t1 = 0.0;
#pragma unroll
        for (int b = 0; b < BB; b += 2) {
            t0 += g_part[k][b * CC + c];
            t1 += g_part[k][(b + 1) * CC + c];
        }
        s[k] = t0 + t1;
    }

    // Raw moments -> central moments (binomial). RNPC = exact 2^-17.
    double q[5];
    {
        const double mux = s[0] * RNPC, M2x = s[1] * RNPC, M3x = s[2] * RNPC,
                     M4x = s[3] * RNPC, M5x = s[4] * RNPC;
        const double muy = s[5] * RNPC, M2y = s[6] * RNPC, M3y = s[7] * RNPC,
                     M4y = s[8] * RNPC, M5y = s[9] * RNPC;
        const double mux2 = mux * mux, mux3 = mux2 * mux;
        const double muy2 = muy * muy, muy3 = muy2 * muy;

        double m2x = M2x - mux2;
        double m3x = M3x - 3.0 * mux * M2x + 2.0 * mux3;
        double m4x = M4x - 4.0 * mux * M3x + 6.0 * mux2 * M2x - 3.0 * mux2 * mux2;
        double m5x = M5x - 5.0 * mux * M4x + 10.0 * mux2 * M3x - 10.0 * mux3 * M2x +
                     4.0 * mux3 * mux2;

        double m2y = M2y - muy2;
        double m3y = M3y - 3.0 * muy * M2y + 2.0 * muy3;
        double m4y = M4y - 4.0 * muy * M3y + 6.0 * muy2 * M2y - 3.0 * muy2 * muy2;
        double m5y = M5y - 5.0 * muy * M4y + 10.0 * muy2 * M3y - 10.0 * muy3 * M2y +
                     4.0 * muy3 * muy2;

        double d0 = mux - muy;
        double d1 = m2x - m2y;
        double d2 = m3x - m3y;
        double d3 = m4x - m4y;
        double d4 = m5x - m5y;
        q[0] = d0 * d0;
        q[1] = d1 * d1;
        q[2] = d2 * d2;
        q[3] = d3 * d3;
        q[4] = d4 * d4;
    }

#pragma unroll
    for (int off = 16; off > 0; off >>= 1) {
#pragma unroll
        for (int k = 0; k < 5; k++)
            q[k] += __shfl_xor_sync(0xFFFFFFFFu, q[k], off);
    }

    __shared__ double red[8][5];
    const int lane = c & 31;
    const int warp = c >> 5;
    if (lane == 0) {
#pragma unroll
        for (int k = 0; k < 5; k++) red[warp][k] = q[k];
    }
    __syncthreads();

    if (c == 0) {
        double loss = 0.0;
#pragma unroll
        for (int k = 0; k < 5; k++) {
            double t = 0.0;
#pragma unroll
            for (int w = 0; w < 8; w++) t += red[w][k];
            loss += sqrt(t);
        }
        out[0] = (float)loss;
    }
}

extern "C" void kernel_launch(void* const* d_in, const int* in_sizes, int n_in,
                              void* d_out, int out_size) {
    const float* x = (const float*)d_in[0];
    const float* y = (const float*)d_in[1];
    float* out = (float*)d_out;
    (void)in_sizes; (void)n_in; (void)out_size;

    moments_kernel<<<2 * PLANES, 256>>>(x, y);
    finalize_kernel<<<1, 256>>>(out);
}